// round 7
// baseline (speedup 1.0000x reference)
#include <cuda_runtime.h>
#include <cuda_bf16.h>
#include <cstdint>
#include <math.h>

#define HW    16384
#define CHW   1048576
#define NTOT  4194304

__device__ float g_buf[9][NTOT];
__device__ float g_mx[256];
__device__ float g_av[256];
__device__ float g_cf[256];
// per conv: 2*TAPS stages (chunk-major) x 8KB
__device__ __align__(16) char g_w3pack[28 * 9 * 16384];
__device__ __align__(16) char g_w5pack[10 * 25 * 16384];

#define SWZ128(o) ((o) ^ (((o) >> 3) & 0x70))

__device__ __forceinline__ uint32_t smem_u32(const void* p) {
    uint32_t a;
    asm("{ .reg .u64 t; cvta.to.shared.u64 t, %1; cvt.u32.u64 %0, t; }" : "=r"(a) : "l"(p));
    return a;
}
#define LDMX4(r, addr) \
    asm volatile("ldmatrix.sync.aligned.m8n8.x4.shared.b16 {%0,%1,%2,%3}, [%4];" \
        : "=r"((r)[0]), "=r"((r)[1]), "=r"((r)[2]), "=r"((r)[3]) : "r"(addr))
#define MMA16816(c, a, b) \
    asm volatile("mma.sync.aligned.m16n8k16.row.col.f32.bf16.bf16.f32 " \
        "{%0,%1,%2,%3}, {%4,%5,%6,%7}, {%8,%9}, {%0,%1,%2,%3};" \
        : "+f"((c)[0]), "+f"((c)[1]), "+f"((c)[2]), "+f"((c)[3]) \
        : "r"((a)[0]), "r"((a)[1]), "r"((a)[2]), "r"((a)[3]), "r"((b)[0]), "r"((b)[1]))
#define CPASYNC16(dst, src) \
    asm volatile("cp.async.ca.shared.global [%0], [%1], 16;" :: "r"(dst), "l"(src))
#define CPCOMMIT() asm volatile("cp.async.commit_group;")

// ---------------- weight prep ----------------
// per (conv, chunk, tap): 8KB tile, stage index s = chunk*TAPS + tap.
// row = oc (64 rows x 128B): [hi: 32 ic x bf16 (64B)][lo: 64B], SWZ128 by row.
__global__ void prep3_kernel(const float* __restrict__ rw, const float* __restrict__ w3,
                             char* __restrict__ dst)
{
    const int t = blockIdx.x, c = blockIdx.y;
    const float* w = (c < 18) ? (rw + (size_t)c * 36864) : (w3 + (size_t)(c - 18) * 36864);
    const float scale = (c < 18) ? (1.0f / 24.0f) : 1.0f;
    char* dconv = dst + (size_t)c * 18 * 8192;
    for (int e = threadIdx.x; e < 4096; e += 256) {
        int oc = e >> 6, ic = e & 63;
        int ch = ic >> 5, icp = ic & 31;
        float v = w[(oc * 64 + ic) * 9 + t] * scale;
        __nv_bfloat16 h = __float2bfloat16(v);
        __nv_bfloat16 l = __float2bfloat16(v - __bfloat162float(h));
        char* d = dconv + ((size_t)ch * 9 + t) * 8192;
        *(unsigned short*)(d + SWZ128((uint32_t)(oc * 128 + icp * 2)))      = __bfloat16_as_ushort(h);
        *(unsigned short*)(d + SWZ128((uint32_t)(oc * 128 + 64 + icp * 2))) = __bfloat16_as_ushort(l);
    }
}
__global__ void prep5_kernel(const float* __restrict__ w5, char* __restrict__ dst)
{
    const int t = blockIdx.x, c = blockIdx.y;
    const float* w = w5 + (size_t)c * 102400;
    char* dconv = dst + (size_t)c * 50 * 8192;
    for (int e = threadIdx.x; e < 4096; e += 256) {
        int oc = e >> 6, ic = e & 63;
        int ch = ic >> 5, icp = ic & 31;
        float v = w[(oc * 64 + ic) * 25 + t];
        __nv_bfloat16 h = __float2bfloat16(v);
        __nv_bfloat16 l = __float2bfloat16(v - __bfloat162float(h));
        char* d = dconv + ((size_t)ch * 25 + t) * 8192;
        *(unsigned short*)(d + SWZ128((uint32_t)(oc * 128 + icp * 2)))      = __bfloat16_as_ushort(h);
        *(unsigned short*)(d + SWZ128((uint32_t)(oc * 128 + 64 + icp * 2))) = __bfloat16_as_ushort(l);
    }
}

// ---------------------------------------------------------------------------
// bf16 HMMA conv, tile 16 x TH, 256 thr = 8 warps (wm 0..3, wn 0..1), 2 CTAs/SM.
// Stages: s = chunk*TAPS + tap (chunk = 32-ic half), 8KB weight tile each,
// triple-buffered cp.async, 1 barrier per stage.  MPW = TH/4 m16-frags/warp.
// acc += Ahi*Bhi + Ahi*Blo + Alo*Bhi (fp32 accum).
// ---------------------------------------------------------------------------
template<int KDIM, int TH, int MOD, int ACT, int RES>
__global__ void __launch_bounds__(256, 2) convMMA_kernel(
    const float* __restrict__ x, const char* __restrict__ wpack,
    const float* __restrict__ bias, const float* __restrict__ cond,
    const float* __restrict__ res, float* __restrict__ out)
{
    constexpr int TAPS = KDIM * KDIM;
    constexpr int NST  = 2 * TAPS;
    constexpr int HALO = KDIM / 2;
    constexpr int IW = 16 + 2 * HALO;
    constexpr int IH = TH + 2 * HALO;
    constexpr int NR = IH * IW;
    constexpr int MPW = TH / 4;

    extern __shared__ __align__(16) char sm[];
    char* actH = sm;
    char* actL = sm + NR * 128;
    char* wts  = sm + 2 * NR * 128;   // 3 x 8KB

    const int tid = threadIdx.x, lane = tid & 31, warp = tid >> 5;
    const int wm = warp & 3, wn = warp >> 2;
    const int gx0 = blockIdx.x * 16, gy0 = blockIdx.y * TH, b = blockIdx.z;
    const int cb = b * 64;
    const float* xb = x + (size_t)b * CHW;

    // ---- stage activation halo tile as bf16 hi/lo (swizzled 128B rows, 64 ic) ----
    for (int e = tid; e < 32 * NR; e += 256) {
        int j = e / NR, p = e - j * NR;
        int iy = p / IW, ix = p - iy * IW;
        int gy = gy0 + iy - HALO, gx = gx0 + ix - HALO;
        float v0 = 0.f, v1 = 0.f;
        if ((unsigned)gy < 128u && (unsigned)gx < 128u) {
            const float* q = xb + (size_t)(2 * j) * HW + gy * 128 + gx;
            v0 = q[0]; v1 = q[HW];
            if (MOD) { v0 *= cond[cb + 2 * j]; v1 *= cond[cb + 2 * j + 1]; }
        }
        __nv_bfloat16 h0 = __float2bfloat16(v0), h1 = __float2bfloat16(v1);
        __nv_bfloat16 l0 = __float2bfloat16(v0 - __bfloat162float(h0));
        __nv_bfloat16 l1 = __float2bfloat16(v1 - __bfloat162float(h1));
        uint32_t off = (uint32_t)p * 128 + ((4u * j) ^ ((uint32_t)(p & 7) << 4));
        *(uint32_t*)(actH + off) = ((uint32_t)__bfloat16_as_ushort(h1) << 16) | __bfloat16_as_ushort(h0);
        *(uint32_t*)(actL + off) = ((uint32_t)__bfloat16_as_ushort(l1) << 16) | __bfloat16_as_ushort(l0);
    }

    const uint32_t actHa = smem_u32(actH);
    const uint32_t actLa = smem_u32(actL);
    const uint32_t wtsA  = smem_u32(wts);

    auto prefetch = [&](int s) {
        const char* src = wpack + (size_t)s * 8192;
        uint32_t dst = wtsA + (uint32_t)(s % 3) * 8192u;
#pragma unroll
        for (int i = 0; i < 2; i++)
            CPASYNC16(dst + (tid + i * 256) * 16, src + (tid + i * 256) * 16);
        CPCOMMIT();
    };
    prefetch(0);
    prefetch(1);

    float c[MPW][4][4];
#pragma unroll
    for (int mi = 0; mi < MPW; mi++)
#pragma unroll
        for (int ni = 0; ni < 4; ni++)
#pragma unroll
            for (int k = 0; k < 4; k++) c[mi][ni][k] = 0.f;

    const int asub = lane >> 3;
    const int arow = ((asub & 1) << 3) + (lane & 7);
    const int ack  = asub >> 1;
    const int bmat = lane >> 3;
    const int bocl = ((bmat >> 1) << 3) + (lane & 7);
    const int bck  = bmat & 1;

    for (int s = 0; s < NST; ++s) {
        if (s == NST - 1) asm volatile("cp.async.wait_group 0;");
        else              asm volatile("cp.async.wait_group 1;");
        __syncthreads();                  // stage-s weights ready; buf (s%3) free of stage s-3 readers
        if (s + 2 < NST) prefetch(s + 2);

        const int chunk = (s >= TAPS) ? 1 : 0;
        const int tap = s - chunk * TAPS;
        const int ky = tap / KDIM, kx = tap - ky * KDIM;
        const uint32_t wb = wtsA + (uint32_t)(s % 3) * 8192u;

#pragma unroll
        for (int kk = 0; kk < 2; ++kk) {
            uint32_t BH[4][2], BL[4][2];
#pragma unroll
            for (int gg = 0; gg < 2; ++gg) {
                int ocr = wn * 32 + gg * 16 + bocl;
                uint32_t base = (uint32_t)ocr * 128;
                uint32_t r[4];
                LDMX4(r, wb + base + ((uint32_t)((kk * 2 + bck) ^ (ocr & 7)) << 4));
                BH[gg * 2][0] = r[0]; BH[gg * 2][1] = r[1];
                BH[gg * 2 + 1][0] = r[2]; BH[gg * 2 + 1][1] = r[3];
                LDMX4(r, wb + base + ((uint32_t)((4 + kk * 2 + bck) ^ (ocr & 7)) << 4));
                BL[gg * 2][0] = r[0]; BL[gg * 2][1] = r[1];
                BL[gg * 2 + 1][0] = r[2]; BL[gg * 2 + 1][1] = r[3];
            }
            const int ksg = chunk * 2 + kk;
#pragma unroll
            for (int mi = 0; mi < MPW; ++mi) {
                uint32_t AH[4], AL[4];
                int rp = (wm * MPW + mi + ky) * IW + arow + kx;
                uint32_t off = (uint32_t)rp * 128 + ((uint32_t)((ksg * 2 + ack) ^ (rp & 7)) << 4);
                LDMX4(AH, actHa + off);
                LDMX4(AL, actLa + off);
#pragma unroll
                for (int ni = 0; ni < 4; ++ni) {
                    MMA16816(c[mi][ni], AH, BH[ni]);
                    MMA16816(c[mi][ni], AH, BL[ni]);
                    MMA16816(c[mi][ni], AL, BH[ni]);
                }
            }
        }
    }

    // ---- epilogue ----
    const int r0 = lane >> 2, q2 = (lane & 3) * 2;
#pragma unroll
    for (int mi = 0; mi < MPW; ++mi) {
        const int y = wm * MPW + mi;
#pragma unroll
        for (int half = 0; half < 2; ++half) {
            const int xcol = r0 + half * 8;
            const int sp = (gy0 + y) * 128 + gx0 + xcol;
#pragma unroll
            for (int ni = 0; ni < 4; ++ni) {
#pragma unroll
                for (int dq = 0; dq < 2; ++dq) {
                    const int n = wn * 32 + ni * 8 + q2 + dq;
                    float v = c[mi][ni][half * 2 + dq];
                    v += MOD ? __ldg(&bias[(cb + n) >> 2]) : __ldg(&bias[n]);
                    if (ACT == 1) v = fmaxf(v, 0.f);
                    if (ACT == 2) v = v > 0.f ? v : 0.01f * v;
                    if (RES) v += __ldg(&res[(size_t)(cb + n) * HW + sp]);
                    out[(size_t)(cb + n) * HW + sp] = v;
                }
            }
        }
    }
}

// ---------------- fp32 1x1 conv ----------------
template<int ACT>
__global__ void __launch_bounds__(256) conv1_kernel(
    const float* __restrict__ x, const float* __restrict__ w,
    const float* __restrict__ bias, float* __restrict__ out)
{
    __shared__ float xs[64][64];
    __shared__ __align__(16) float ws[64][68];
    const int tid = threadIdx.x;
    const int b  = blockIdx.y;
    const int p0 = blockIdx.x * 64;
    for (int e = tid; e < 4096; e += 256) {
        int ic = e >> 6, px = e & 63;
        xs[ic][px] = x[(size_t)b * CHW + ic * HW + p0 + px];
    }
    for (int e = tid; e < 4096; e += 256) {
        int ocw = e >> 6, ic = e & 63;
        ws[ic][ocw] = w[ocw * 64 + ic];
    }
    __syncthreads();
    const int px = tid & 63;
    const int oc0 = (tid >> 6) * 16;
    float acc[16];
#pragma unroll
    for (int o = 0; o < 16; o++) acc[o] = 0.f;
#pragma unroll 4
    for (int ic = 0; ic < 64; ic++) {
        float xv = xs[ic][px];
        const float4* wr = (const float4*)&ws[ic][oc0];
        float4 w0 = wr[0], w1 = wr[1], w2 = wr[2], w3 = wr[3];
        acc[0]+=xv*w0.x; acc[1]+=xv*w0.y; acc[2]+=xv*w0.z; acc[3]+=xv*w0.w;
        acc[4]+=xv*w1.x; acc[5]+=xv*w1.y; acc[6]+=xv*w1.z; acc[7]+=xv*w1.w;
        acc[8]+=xv*w2.x; acc[9]+=xv*w2.y; acc[10]+=xv*w2.z; acc[11]+=xv*w2.w;
        acc[12]+=xv*w3.x; acc[13]+=xv*w3.y; acc[14]+=xv*w3.z; acc[15]+=xv*w3.w;
    }
#pragma unroll
    for (int o = 0; o < 16; o++) {
        float v = acc[o] + bias[oc0 + o];
        if (ACT == 2) v = v > 0.f ? v : 0.01f * v;
        out[(size_t)b * CHW + (oc0 + o) * HW + p0 + px] = v;
    }
}

// ---------------- small kernels ----------------
__global__ void pool_kernel(const float* __restrict__ x, float* __restrict__ mx, float* __restrict__ av)
{
    const int bc = blockIdx.x;
    const float* p = x + (size_t)bc * HW;
    float m = -3.402823466e38f, s = 0.f;
    for (int i = threadIdx.x; i < HW; i += 256) { float v = p[i]; m = fmaxf(m, v); s += v; }
#pragma unroll
    for (int o = 16; o; o >>= 1) {
        m = fmaxf(m, __shfl_xor_sync(0xFFFFFFFFu, m, o));
        s += __shfl_xor_sync(0xFFFFFFFFu, s, o);
    }
    __shared__ float sm_[8], ss_[8];
    int wid = threadIdx.x >> 5;
    if ((threadIdx.x & 31) == 0) { sm_[wid] = m; ss_[wid] = s; }
    __syncthreads();
    if (threadIdx.x == 0) {
        float mm = sm_[0], st = ss_[0];
        for (int i = 1; i < 8; i++) { mm = fmaxf(mm, sm_[i]); st += ss_[i]; }
        mx[bc] = mm; av[bc] = st * (1.0f / 16384.0f);
    }
}
__global__ void coef_kernel(const float* __restrict__ mx, const float* __restrict__ av,
                            const float* __restrict__ cw1, const float* __restrict__ cw2,
                            const float* __restrict__ fw, const float* __restrict__ fb,
                            float* __restrict__ coef)
{
    __shared__ float hm[16], ha[16];
    int t = threadIdx.x;
    if (t < 32) {
        int which = t >> 4, t2 = t & 15, b = t2 >> 2, j = t2 & 3;
        const float* v = which ? av : mx;
        float s = 0.f;
        for (int c = 0; c < 64; c++) s += v[b * 64 + c] * cw1[j * 64 + c];
        s = fmaxf(s, 0.f);
        if (which) ha[t2] = s; else hm[t2] = s;
    }
    __syncthreads();
    int b = t >> 6, c = t & 63;
    float se_m = 0.f, se_a = 0.f;
#pragma unroll
    for (int j = 0; j < 4; j++) {
        se_m += hm[b * 4 + j] * cw2[c * 4 + j];
        se_a += ha[b * 4 + j] * cw2[c * 4 + j];
    }
    float xll = 1.f / (1.f + expf(-(se_m + se_a)));
    coef[t] = fw[1] * (fw[0] * xll + fb[0]) + fb[1];
}
__global__ void combine_kernel(const float* __restrict__ s1, const float* __restrict__ s3,
                               const float* __restrict__ s5, const float* __restrict__ coef,
                               float* __restrict__ out)
{
    int fi = (blockIdx.x * 256 + threadIdx.x) * 4;
    float cf = coef[fi >> 14];
    float4 a = *(const float4*)(s1 + fi);
    float4 b = *(const float4*)(s3 + fi);
    float4 c = *(const float4*)(s5 + fi);
    float4 r;
    r.x = cf * (a.x + b.x + c.x); r.y = cf * (a.y + b.y + c.y);
    r.z = cf * (a.z + b.z + c.z); r.w = cf * (a.w + b.w + c.w);
    *(float4*)(out + fi) = r;
}
__global__ void add_kernel(float* __restrict__ a, const float* __restrict__ b)
{
    int fi = (blockIdx.x * 256 + threadIdx.x) * 4;
    float4 u = *(float4*)(a + fi);
    float4 v = *(const float4*)(b + fi);
    u.x += v.x; u.y += v.y; u.z += v.z; u.w += v.w;
    *(float4*)(a + fi) = u;
}
__global__ void mapmul_kernel(float* __restrict__ a, const float* __restrict__ mp)
{
    int fi = (blockIdx.x * 256 + threadIdx.x) * 4;
    int b = fi >> 20, s = fi & (HW - 1);
    float4 m = *(const float4*)(mp + b * HW + s);
    float4 v = *(float4*)(a + fi);
    v.x *= (1.f + m.x); v.y *= (1.f + m.y); v.z *= (1.f + m.z); v.w *= (1.f + m.w);
    *(float4*)(a + fi) = v;
}

// ---------------- launch ----------------
template<int KDIM, int TH, int MOD, int ACT, int RES>
static void launch_conv(const float* x, const char* wp, const float* bias,
                        const float* cond, const float* res, float* out)
{
    constexpr int HALO = KDIM / 2;
    constexpr int NR = (TH + 2 * HALO) * (16 + 2 * HALO);
    constexpr int SMEMB = 2 * NR * 128 + 3 * 8192;
    cudaFuncSetAttribute(convMMA_kernel<KDIM, TH, MOD, ACT, RES>,
                         cudaFuncAttributeMaxDynamicSharedMemorySize, SMEMB);
    convMMA_kernel<KDIM, TH, MOD, ACT, RES><<<dim3(8, 128 / TH, 4), 256, SMEMB>>>(x, wp, bias, cond, res, out);
}

extern "C" void kernel_launch(void* const* d_in, const int* in_sizes, int n_in,
                              void* d_out, int out_size)
{
    (void)in_sizes; (void)n_in; (void)out_size;
    const float* x   = (const float*)d_in[0];
    const float* c1  = (const float*)d_in[1];
    const float* c2  = (const float*)d_in[2];
    const float* mp  = (const float*)d_in[3];
    const float* rw  = (const float*)d_in[4];
    const float* rb  = (const float*)d_in[5];
    const float* w1  = (const float*)d_in[6];
    const float* b1  = (const float*)d_in[7];
    const float* w3  = (const float*)d_in[8];
    const float* b3  = (const float*)d_in[9];
    const float* w5  = (const float*)d_in[10];
    const float* b5  = (const float*)d_in[11];
    const float* cw1 = (const float*)d_in[12];
    const float* cw2 = (const float*)d_in[13];
    const float* fw  = (const float*)d_in[14];
    const float* fb  = (const float*)d_in[15];
    float* OUT = (float*)d_out;

    float* base;  cudaGetSymbolAddress((void**)&base, g_buf);
    char* W3P;    cudaGetSymbolAddress((void**)&W3P, g_w3pack);
    char* W5P;    cudaGetSymbolAddress((void**)&W5P, g_w5pack);
    float *MX, *AV, *CF;
    cudaGetSymbolAddress((void**)&MX, g_mx);
    cudaGetSymbolAddress((void**)&AV, g_av);
    cudaGetSymbolAddress((void**)&CF, g_cf);

    float* CUR = base;
    float* TMP = base + (size_t)NTOT;
    float* S1  = base + 2 * (size_t)NTOT;
    float* S3  = base + 3 * (size_t)NTOT;
    float* S5  = base + 4 * (size_t)NTOT;
    float* E1  = base + 5 * (size_t)NTOT;
    float* E2  = base + 6 * (size_t)NTOT;
    float* E3  = base + 7 * (size_t)NTOT;
    float* E4  = base + 8 * (size_t)NTOT;

    prep3_kernel<<<dim3(9, 28), 256>>>(rw, w3, W3P);
    prep5_kernel<<<dim3(25, 10), 256>>>(w5, W5P);

    const dim3 G1(256, 4);
    const int EG = NTOT / 4 / 256;

    auto resb = [&](const float* in, float* out, int i, const float* cond) {
        const char* wp = W3P + (size_t)(i * 2) * 18 * 8192;
        const float* bi = rb + (size_t)i * 2 * 64;
        launch_conv<3, 16, 1, 1, 0>(in, wp, bi, cond, nullptr, TMP);
        launch_conv<3, 16, 1, 0, 1>(TMP, wp + 18 * 8192, bi + 64, cond + 256, in, out);
    };
    auto mfe = [&](int i) {
        pool_kernel<<<256, 256>>>(CUR, MX, AV);
        coef_kernel<<<1, 256>>>(MX, AV, cw1 + i * 256, cw2 + i * 256, fw + i * 2, fb + i * 2, CF);
        const float* w1i = w1 + (size_t)i * 2 * 64 * 64;
        const char* w3p = W3P + (size_t)(18 + i * 2) * 18 * 8192;
        const char* w5p = W5P + (size_t)(i * 2) * 50 * 8192;
        conv1_kernel<2><<<G1, 256>>>(CUR, w1i, b1 + i * 128, TMP);
        conv1_kernel<0><<<G1, 256>>>(TMP, w1i + 64 * 64, b1 + i * 128 + 64, S1);
        launch_conv<3, 16, 0, 2, 0>(CUR, w3p, b3 + i * 128, nullptr, nullptr, TMP);
        launch_conv<3, 16, 0, 0, 0>(TMP, w3p + 18 * 8192, b3 + i * 128 + 64, nullptr, nullptr, S3);
        launch_conv<5, 8, 0, 2, 0>(CUR, w5p, b5 + i * 128, nullptr, nullptr, TMP);
        launch_conv<5, 8, 0, 0, 0>(TMP, w5p + 50 * 8192, b5 + i * 128 + 64, nullptr, nullptr, S5);
        combine_kernel<<<EG, 256>>>(S1, S3, S5, CF, CUR);
    };

    const size_t NB = (size_t)NTOT * sizeof(float);

    resb(x, CUR, 0, c1); mfe(0); resb(CUR, CUR, 0, c1);
    cudaMemcpyAsync(E1, CUR, NB, cudaMemcpyDeviceToDevice);

    for (int k = 0; k < 3; k++) resb(CUR, CUR, 1, c1 + 512);
    cudaMemcpyAsync(E2, CUR, NB, cudaMemcpyDeviceToDevice);

    resb(CUR, CUR, 2, c1 + 1024); mfe(1); resb(CUR, CUR, 2, c1 + 1024);
    cudaMemcpyAsync(E3, CUR, NB, cudaMemcpyDeviceToDevice);

    for (int k = 0; k < 3; k++) resb(CUR, CUR, 3, c1 + 1536);
    cudaMemcpyAsync(E4, CUR, NB, cudaMemcpyDeviceToDevice);

    resb(CUR, CUR, 4, c2); mfe(2);
    mapmul_kernel<<<EG, 256>>>(CUR, mp);
    resb(CUR, CUR, 4, c2);
    add_kernel<<<EG, 256>>>(CUR, E4);

    for (int k = 0; k < 3; k++) resb(CUR, CUR, 5, c1 + 5 * 512);

    add_kernel<<<EG, 256>>>(CUR, E3);
    resb(CUR, CUR, 6, c1 + 6 * 512); mfe(3); resb(CUR, CUR, 6, c1 + 6 * 512);

    add_kernel<<<EG, 256>>>(CUR, E2);
    for (int k = 0; k < 3; k++) resb(CUR, CUR, 7, c1 + 7 * 512);

    add_kernel<<<EG, 256>>>(CUR, E1);
    resb(CUR, CUR, 8, c1 + 8 * 512);
    mfe(4);
    {
        const char* wp = W3P + (size_t)(8 * 2) * 18 * 8192;
        const float* bi = rb + (size_t)8 * 2 * 64;
        const float* cond = c1 + 8 * 512;
        launch_conv<3, 16, 1, 1, 0>(CUR, wp, bi, cond, nullptr, TMP);
        launch_conv<3, 16, 1, 0, 1>(TMP, wp + 18 * 8192, bi + 64, cond + 256, CUR, OUT);
    }
}

// round 8
// speedup vs baseline: 1.0063x; 1.0063x over previous
#include <cuda_runtime.h>
#include <cuda_bf16.h>
#include <cstdint>
#include <math.h>

#define HW    16384
#define CHW   1048576
#define NTOT  4194304

__device__ float g_buf[9][NTOT];
__device__ float g_mx[256];
__device__ float g_av[256];
__device__ float g_cf[256];
// per conv: 2*TAPS stages (chunk-major) x 8KB
__device__ __align__(16) char g_w3pack[28 * 9 * 16384];
__device__ __align__(16) char g_w5pack[10 * 25 * 16384];

#define SWZ128(o) ((o) ^ (((o) >> 3) & 0x70))

__device__ __forceinline__ uint32_t smem_u32(const void* p) {
    uint32_t a;
    asm("{ .reg .u64 t; cvta.to.shared.u64 t, %1; cvt.u32.u64 %0, t; }" : "=r"(a) : "l"(p));
    return a;
}
#define LDMX4(r, addr) \
    asm volatile("ldmatrix.sync.aligned.m8n8.x4.shared.b16 {%0,%1,%2,%3}, [%4];" \
        : "=r"((r)[0]), "=r"((r)[1]), "=r"((r)[2]), "=r"((r)[3]) : "r"(addr))
#define MMA16816(c, a, b) \
    asm volatile("mma.sync.aligned.m16n8k16.row.col.f32.bf16.bf16.f32 " \
        "{%0,%1,%2,%3}, {%4,%5,%6,%7}, {%8,%9}, {%0,%1,%2,%3};" \
        : "+f"((c)[0]), "+f"((c)[1]), "+f"((c)[2]), "+f"((c)[3]) \
        : "r"((a)[0]), "r"((a)[1]), "r"((a)[2]), "r"((a)[3]), "r"((b)[0]), "r"((b)[1]))
#define CPASYNC16(dst, src) \
    asm volatile("cp.async.ca.shared.global [%0], [%1], 16;" :: "r"(dst), "l"(src))
#define CPCOMMIT() asm volatile("cp.async.commit_group;")

// ---------------- weight prep ----------------
// per (conv, chunk, tap): 8KB tile, stage index s = chunk*TAPS + tap.
// row = oc (64 rows x 128B): [hi: 32 ic x bf16 (64B)][lo: 64B], SWZ128 by row.
__global__ void prep3_kernel(const float* __restrict__ rw, const float* __restrict__ w3,
                             char* __restrict__ dst)
{
    const int t = blockIdx.x, c = blockIdx.y;
    const float* w = (c < 18) ? (rw + (size_t)c * 36864) : (w3 + (size_t)(c - 18) * 36864);
    const float scale = (c < 18) ? (1.0f / 24.0f) : 1.0f;
    char* dconv = dst + (size_t)c * 18 * 8192;
    for (int e = threadIdx.x; e < 4096; e += 256) {
        int oc = e >> 6, ic = e & 63;
        int ch = ic >> 5, icp = ic & 31;
        float v = w[(oc * 64 + ic) * 9 + t] * scale;
        __nv_bfloat16 h = __float2bfloat16(v);
        __nv_bfloat16 l = __float2bfloat16(v - __bfloat162float(h));
        char* d = dconv + ((size_t)ch * 9 + t) * 8192;
        *(unsigned short*)(d + SWZ128((uint32_t)(oc * 128 + icp * 2)))      = __bfloat16_as_ushort(h);
        *(unsigned short*)(d + SWZ128((uint32_t)(oc * 128 + 64 + icp * 2))) = __bfloat16_as_ushort(l);
    }
}
__global__ void prep5_kernel(const float* __restrict__ w5, char* __restrict__ dst)
{
    const int t = blockIdx.x, c = blockIdx.y;
    const float* w = w5 + (size_t)c * 102400;
    char* dconv = dst + (size_t)c * 50 * 8192;
    for (int e = threadIdx.x; e < 4096; e += 256) {
        int oc = e >> 6, ic = e & 63;
        int ch = ic >> 5, icp = ic & 31;
        float v = w[(oc * 64 + ic) * 25 + t];
        __nv_bfloat16 h = __float2bfloat16(v);
        __nv_bfloat16 l = __float2bfloat16(v - __bfloat162float(h));
        char* d = dconv + ((size_t)ch * 25 + t) * 8192;
        *(unsigned short*)(d + SWZ128((uint32_t)(oc * 128 + icp * 2)))      = __bfloat16_as_ushort(h);
        *(unsigned short*)(d + SWZ128((uint32_t)(oc * 128 + 64 + icp * 2))) = __bfloat16_as_ushort(l);
    }
}

// ---------------------------------------------------------------------------
// bf16 HMMA conv, tile 16 x TH, 256 thr = 8 warps (wm 0..3, wn 0..1), 2 CTAs/SM.
// Stages: s = chunk*TAPS + tap (chunk = 32-ic half), 8KB weight tile each,
// triple-buffered cp.async, 1 barrier per stage.  MPW = TH/4 m16-frags/warp.
// acc += Ahi*Bhi + Ahi*Blo + Alo*Bhi (fp32 accum).
// ---------------------------------------------------------------------------
template<int KDIM, int TH, int MOD, int ACT, int RES>
__global__ void __launch_bounds__(256, 2) convMMA_kernel(
    const float* __restrict__ x, const char* __restrict__ wpack,
    const float* __restrict__ bias, const float* __restrict__ cond,
    const float* __restrict__ res, float* __restrict__ out)
{
    constexpr int TAPS = KDIM * KDIM;
    constexpr int NST  = 2 * TAPS;
    constexpr int HALO = KDIM / 2;
    constexpr int IW = 16 + 2 * HALO;
    constexpr int IH = TH + 2 * HALO;
    constexpr int NR = IH * IW;
    constexpr int MPW = TH / 4;

    extern __shared__ __align__(16) char sm[];
    char* actH = sm;
    char* actL = sm + NR * 128;
    char* wts  = sm + 2 * NR * 128;   // 3 x 8KB

    const int tid = threadIdx.x, lane = tid & 31, warp = tid >> 5;
    const int wm = warp & 3, wn = warp >> 2;
    const int gx0 = blockIdx.x * 16, gy0 = blockIdx.y * TH, b = blockIdx.z;
    const int cb = b * 64;
    const float* xb = x + (size_t)b * CHW;

    // ---- stage activation halo tile as bf16 hi/lo (swizzled 128B rows, 64 ic) ----
    for (int e = tid; e < 32 * NR; e += 256) {
        int j = e / NR, p = e - j * NR;
        int iy = p / IW, ix = p - iy * IW;
        int gy = gy0 + iy - HALO, gx = gx0 + ix - HALO;
        float v0 = 0.f, v1 = 0.f;
        if ((unsigned)gy < 128u && (unsigned)gx < 128u) {
            const float* q = xb + (size_t)(2 * j) * HW + gy * 128 + gx;
            v0 = q[0]; v1 = q[HW];
            if (MOD) { v0 *= cond[cb + 2 * j]; v1 *= cond[cb + 2 * j + 1]; }
        }
        __nv_bfloat16 h0 = __float2bfloat16(v0), h1 = __float2bfloat16(v1);
        __nv_bfloat16 l0 = __float2bfloat16(v0 - __bfloat162float(h0));
        __nv_bfloat16 l1 = __float2bfloat16(v1 - __bfloat162float(h1));
        uint32_t off = (uint32_t)p * 128 + ((4u * j) ^ ((uint32_t)(p & 7) << 4));
        *(uint32_t*)(actH + off) = ((uint32_t)__bfloat16_as_ushort(h1) << 16) | __bfloat16_as_ushort(h0);
        *(uint32_t*)(actL + off) = ((uint32_t)__bfloat16_as_ushort(l1) << 16) | __bfloat16_as_ushort(l0);
    }

    const uint32_t actHa = smem_u32(actH);
    const uint32_t actLa = smem_u32(actL);
    const uint32_t wtsA  = smem_u32(wts);

    auto prefetch = [&](int s) {
        const char* src = wpack + (size_t)s * 8192;
        uint32_t dst = wtsA + (uint32_t)(s % 3) * 8192u;
#pragma unroll
        for (int i = 0; i < 2; i++)
            CPASYNC16(dst + (tid + i * 256) * 16, src + (tid + i * 256) * 16);
        CPCOMMIT();
    };
    prefetch(0);
    prefetch(1);

    float c[MPW][4][4];
#pragma unroll
    for (int mi = 0; mi < MPW; mi++)
#pragma unroll
        for (int ni = 0; ni < 4; ni++)
#pragma unroll
            for (int k = 0; k < 4; k++) c[mi][ni][k] = 0.f;

    const int asub = lane >> 3;
    const int arow = ((asub & 1) << 3) + (lane & 7);
    const int ack  = asub >> 1;
    const int bmat = lane >> 3;
    const int bocl = ((bmat >> 1) << 3) + (lane & 7);
    const int bck  = bmat & 1;

    for (int s = 0; s < NST; ++s) {
        if (s == NST - 1) asm volatile("cp.async.wait_group 0;");
        else              asm volatile("cp.async.wait_group 1;");
        __syncthreads();                  // stage-s weights ready; buf (s%3) free of stage s-3 readers
        if (s + 2 < NST) prefetch(s + 2);

        const int chunk = (s >= TAPS) ? 1 : 0;
        const int tap = s - chunk * TAPS;
        const int ky = tap / KDIM, kx = tap - ky * KDIM;
        const uint32_t wb = wtsA + (uint32_t)(s % 3) * 8192u;

#pragma unroll
        for (int kk = 0; kk < 2; ++kk) {
            uint32_t BH[4][2], BL[4][2];
#pragma unroll
            for (int gg = 0; gg < 2; ++gg) {
                int ocr = wn * 32 + gg * 16 + bocl;
                uint32_t base = (uint32_t)ocr * 128;
                uint32_t r[4];
                LDMX4(r, wb + base + ((uint32_t)((kk * 2 + bck) ^ (ocr & 7)) << 4));
                BH[gg * 2][0] = r[0]; BH[gg * 2][1] = r[1];
                BH[gg * 2 + 1][0] = r[2]; BH[gg * 2 + 1][1] = r[3];
                LDMX4(r, wb + base + ((uint32_t)((4 + kk * 2 + bck) ^ (ocr & 7)) << 4));
                BL[gg * 2][0] = r[0]; BL[gg * 2][1] = r[1];
                BL[gg * 2 + 1][0] = r[2]; BL[gg * 2 + 1][1] = r[3];
            }
            const int ksg = chunk * 2 + kk;
#pragma unroll
            for (int mi = 0; mi < MPW; ++mi) {
                uint32_t AH[4], AL[4];
                int rp = (wm * MPW + mi + ky) * IW + arow + kx;
                uint32_t off = (uint32_t)rp * 128 + ((uint32_t)((ksg * 2 + ack) ^ (rp & 7)) << 4);
                LDMX4(AH, actHa + off);
                LDMX4(AL, actLa + off);
#pragma unroll
                for (int ni = 0; ni < 4; ++ni) {
                    MMA16816(c[mi][ni], AH, BH[ni]);
                    MMA16816(c[mi][ni], AH, BL[ni]);
                    MMA16816(c[mi][ni], AL, BH[ni]);
                }
            }
        }
    }

    // ---- epilogue ----
    const int r0 = lane >> 2, q2 = (lane & 3) * 2;
#pragma unroll
    for (int mi = 0; mi < MPW; ++mi) {
        const int y = wm * MPW + mi;
#pragma unroll
        for (int half = 0; half < 2; ++half) {
            const int xcol = r0 + half * 8;
            const int sp = (gy0 + y) * 128 + gx0 + xcol;
#pragma unroll
            for (int ni = 0; ni < 4; ++ni) {
#pragma unroll
                for (int dq = 0; dq < 2; ++dq) {
                    const int n = wn * 32 + ni * 8 + q2 + dq;
                    float v = c[mi][ni][half * 2 + dq];
                    v += MOD ? __ldg(&bias[(cb + n) >> 2]) : __ldg(&bias[n]);
                    if (ACT == 1) v = fmaxf(v, 0.f);
                    if (ACT == 2) v = v > 0.f ? v : 0.01f * v;
                    if (RES) v += __ldg(&res[(size_t)(cb + n) * HW + sp]);
                    out[(size_t)(cb + n) * HW + sp] = v;
                }
            }
        }
    }
}

// ---------------- fp32 1x1 conv ----------------
template<int ACT>
__global__ void __launch_bounds__(256) conv1_kernel(
    const float* __restrict__ x, const float* __restrict__ w,
    const float* __restrict__ bias, float* __restrict__ out)
{
    __shared__ float xs[64][64];
    __shared__ __align__(16) float ws[64][68];
    const int tid = threadIdx.x;
    const int b  = blockIdx.y;
    const int p0 = blockIdx.x * 64;
    for (int e = tid; e < 4096; e += 256) {
        int ic = e >> 6, px = e & 63;
        xs[ic][px] = x[(size_t)b * CHW + ic * HW + p0 + px];
    }
    for (int e = tid; e < 4096; e += 256) {
        int ocw = e >> 6, ic = e & 63;
        ws[ic][ocw] = w[ocw * 64 + ic];
    }
    __syncthreads();
    const int px = tid & 63;
    const int oc0 = (tid >> 6) * 16;
    float acc[16];
#pragma unroll
    for (int o = 0; o < 16; o++) acc[o] = 0.f;
#pragma unroll 4
    for (int ic = 0; ic < 64; ic++) {
        float xv = xs[ic][px];
        const float4* wr = (const float4*)&ws[ic][oc0];
        float4 w0 = wr[0], w1 = wr[1], w2 = wr[2], w3 = wr[3];
        acc[0]+=xv*w0.x; acc[1]+=xv*w0.y; acc[2]+=xv*w0.z; acc[3]+=xv*w0.w;
        acc[4]+=xv*w1.x; acc[5]+=xv*w1.y; acc[6]+=xv*w1.z; acc[7]+=xv*w1.w;
        acc[8]+=xv*w2.x; acc[9]+=xv*w2.y; acc[10]+=xv*w2.z; acc[11]+=xv*w2.w;
        acc[12]+=xv*w3.x; acc[13]+=xv*w3.y; acc[14]+=xv*w3.z; acc[15]+=xv*w3.w;
    }
#pragma unroll
    for (int o = 0; o < 16; o++) {
        float v = acc[o] + bias[oc0 + o];
        if (ACT == 2) v = v > 0.f ? v : 0.01f * v;
        out[(size_t)b * CHW + (oc0 + o) * HW + p0 + px] = v;
    }
}

// ---------------- small kernels ----------------
__global__ void pool_kernel(const float* __restrict__ x, float* __restrict__ mx, float* __restrict__ av)
{
    const int bc = blockIdx.x;
    const float* p = x + (size_t)bc * HW;
    float m = -3.402823466e38f, s = 0.f;
    for (int i = threadIdx.x; i < HW; i += 256) { float v = p[i]; m = fmaxf(m, v); s += v; }
#pragma unroll
    for (int o = 16; o; o >>= 1) {
        m = fmaxf(m, __shfl_xor_sync(0xFFFFFFFFu, m, o));
        s += __shfl_xor_sync(0xFFFFFFFFu, s, o);
    }
    __shared__ float sm_[8], ss_[8];
    int wid = threadIdx.x >> 5;
    if ((threadIdx.x & 31) == 0) { sm_[wid] = m; ss_[wid] = s; }
    __syncthreads();
    if (threadIdx.x == 0) {
        float mm = sm_[0], st = ss_[0];
        for (int i = 1; i < 8; i++) { mm = fmaxf(mm, sm_[i]); st += ss_[i]; }
        mx[bc] = mm; av[bc] = st * (1.0f / 16384.0f);
    }
}
__global__ void coef_kernel(const float* __restrict__ mx, const float* __restrict__ av,
                            const float* __restrict__ cw1, const float* __restrict__ cw2,
                            const float* __restrict__ fw, const float* __restrict__ fb,
                            float* __restrict__ coef)
{
    __shared__ float hm[16], ha[16];
    int t = threadIdx.x;
    if (t < 32) {
        int which = t >> 4, t2 = t & 15, b = t2 >> 2, j = t2 & 3;
        const float* v = which ? av : mx;
        float s = 0.f;
        for (int c = 0; c < 64; c++) s += v[b * 64 + c] * cw1[j * 64 + c];
        s = fmaxf(s, 0.f);
        if (which) ha[t2] = s; else hm[t2] = s;
    }
    __syncthreads();
    int b = t >> 6, c = t & 63;
    float se_m = 0.f, se_a = 0.f;
#pragma unroll
    for (int j = 0; j < 4; j++) {
        se_m += hm[b * 4 + j] * cw2[c * 4 + j];
        se_a += ha[b * 4 + j] * cw2[c * 4 + j];
    }
    float xll = 1.f / (1.f + expf(-(se_m + se_a)));
    coef[t] = fw[1] * (fw[0] * xll + fb[0]) + fb[1];
}
__global__ void combine_kernel(const float* __restrict__ s1, const float* __restrict__ s3,
                               const float* __restrict__ s5, const float* __restrict__ coef,
                               float* __restrict__ out)
{
    int fi = (blockIdx.x * 256 + threadIdx.x) * 4;
    float cf = coef[fi >> 14];
    float4 a = *(const float4*)(s1 + fi);
    float4 b = *(const float4*)(s3 + fi);
    float4 c = *(const float4*)(s5 + fi);
    float4 r;
    r.x = cf * (a.x + b.x + c.x); r.y = cf * (a.y + b.y + c.y);
    r.z = cf * (a.z + b.z + c.z); r.w = cf * (a.w + b.w + c.w);
    *(float4*)(out + fi) = r;
}
__global__ void add_kernel(float* __restrict__ a, const float* __restrict__ b)
{
    int fi = (blockIdx.x * 256 + threadIdx.x) * 4;
    float4 u = *(float4*)(a + fi);
    float4 v = *(const float4*)(b + fi);
    u.x += v.x; u.y += v.y; u.z += v.z; u.w += v.w;
    *(float4*)(a + fi) = u;
}
__global__ void mapmul_kernel(float* __restrict__ a, const float* __restrict__ mp)
{
    int fi = (blockIdx.x * 256 + threadIdx.x) * 4;
    int b = fi >> 20, s = fi & (HW - 1);
    float4 m = *(const float4*)(mp + b * HW + s);
    float4 v = *(float4*)(a + fi);
    v.x *= (1.f + m.x); v.y *= (1.f + m.y); v.z *= (1.f + m.z); v.w *= (1.f + m.w);
    *(float4*)(a + fi) = v;
}

// ---------------- launch ----------------
template<int KDIM, int TH, int MOD, int ACT, int RES>
static void launch_conv(const float* x, const char* wp, const float* bias,
                        const float* cond, const float* res, float* out)
{
    constexpr int HALO = KDIM / 2;
    constexpr int NR = (TH + 2 * HALO) * (16 + 2 * HALO);
    constexpr int SMEMB = 2 * NR * 128 + 3 * 8192;
    cudaFuncSetAttribute(convMMA_kernel<KDIM, TH, MOD, ACT, RES>,
                         cudaFuncAttributeMaxDynamicSharedMemorySize, SMEMB);
    convMMA_kernel<KDIM, TH, MOD, ACT, RES><<<dim3(8, 128 / TH, 4), 256, SMEMB>>>(x, wp, bias, cond, res, out);
}

extern "C" void kernel_launch(void* const* d_in, const int* in_sizes, int n_in,
                              void* d_out, int out_size)
{
    (void)in_sizes; (void)n_in; (void)out_size;
    const float* x   = (const float*)d_in[0];
    const float* c1  = (const float*)d_in[1];
    const float* c2  = (const float*)d_in[2];
    const float* mp  = (const float*)d_in[3];
    const float* rw  = (const float*)d_in[4];
    const float* rb  = (const float*)d_in[5];
    const float* w1  = (const float*)d_in[6];
    const float* b1  = (const float*)d_in[7];
    const float* w3  = (const float*)d_in[8];
    const float* b3  = (const float*)d_in[9];
    const float* w5  = (const float*)d_in[10];
    const float* b5  = (const float*)d_in[11];
    const float* cw1 = (const float*)d_in[12];
    const float* cw2 = (const float*)d_in[13];
    const float* fw  = (const float*)d_in[14];
    const float* fb  = (const float*)d_in[15];
    float* OUT = (float*)d_out;

    float* base;  cudaGetSymbolAddress((void**)&base, g_buf);
    char* W3P;    cudaGetSymbolAddress((void**)&W3P, g_w3pack);
    char* W5P;    cudaGetSymbolAddress((void**)&W5P, g_w5pack);
    float *MX, *AV, *CF;
    cudaGetSymbolAddress((void**)&MX, g_mx);
    cudaGetSymbolAddress((void**)&AV, g_av);
    cudaGetSymbolAddress((void**)&CF, g_cf);

    float* CUR = base;
    float* TMP = base + (size_t)NTOT;
    float* S1  = base + 2 * (size_t)NTOT;
    float* S3  = base + 3 * (size_t)NTOT;
    float* S5  = base + 4 * (size_t)NTOT;
    float* E1  = base + 5 * (size_t)NTOT;
    float* E2  = base + 6 * (size_t)NTOT;
    float* E3  = base + 7 * (size_t)NTOT;
    float* E4  = base + 8 * (size_t)NTOT;

    prep3_kernel<<<dim3(9, 28), 256>>>(rw, w3, W3P);
    prep5_kernel<<<dim3(25, 10), 256>>>(w5, W5P);

    const dim3 G1(256, 4);
    const int EG = NTOT / 4 / 256;

    auto resb = [&](const float* in, float* out, int i, const float* cond) {
        const char* wp = W3P + (size_t)(i * 2) * 18 * 8192;
        const float* bi = rb + (size_t)i * 2 * 64;
        launch_conv<3, 16, 1, 1, 0>(in, wp, bi, cond, nullptr, TMP);
        launch_conv<3, 16, 1, 0, 1>(TMP, wp + 18 * 8192, bi + 64, cond + 256, in, out);
    };
    auto mfe = [&](int i) {
        pool_kernel<<<256, 256>>>(CUR, MX, AV);
        coef_kernel<<<1, 256>>>(MX, AV, cw1 + i * 256, cw2 + i * 256, fw + i * 2, fb + i * 2, CF);
        const float* w1i = w1 + (size_t)i * 2 * 64 * 64;
        const char* w3p = W3P + (size_t)(18 + i * 2) * 18 * 8192;
        const char* w5p = W5P + (size_t)(i * 2) * 50 * 8192;
        conv1_kernel<2><<<G1, 256>>>(CUR, w1i, b1 + i * 128, TMP);
        conv1_kernel<0><<<G1, 256>>>(TMP, w1i + 64 * 64, b1 + i * 128 + 64, S1);
        launch_conv<3, 16, 0, 2, 0>(CUR, w3p, b3 + i * 128, nullptr, nullptr, TMP);
        launch_conv<3, 16, 0, 0, 0>(TMP, w3p + 18 * 8192, b3 + i * 128 + 64, nullptr, nullptr, S3);
        launch_conv<5, 8, 0, 2, 0>(CUR, w5p, b5 + i * 128, nullptr, nullptr, TMP);
        launch_conv<5, 8, 0, 0, 0>(TMP, w5p + 50 * 8192, b5 + i * 128 + 64, nullptr, nullptr, S5);
        combine_kernel<<<EG, 256>>>(S1, S3, S5, CF, CUR);
    };

    const size_t NB = (size_t)NTOT * sizeof(float);

    resb(x, CUR, 0, c1); mfe(0); resb(CUR, CUR, 0, c1);
    cudaMemcpyAsync(E1, CUR, NB, cudaMemcpyDeviceToDevice);

    for (int k = 0; k < 3; k++) resb(CUR, CUR, 1, c1 + 512);
    cudaMemcpyAsync(E2, CUR, NB, cudaMemcpyDeviceToDevice);

    resb(CUR, CUR, 2, c1 + 1024); mfe(1); resb(CUR, CUR, 2, c1 + 1024);
    cudaMemcpyAsync(E3, CUR, NB, cudaMemcpyDeviceToDevice);

    for (int k = 0; k < 3; k++) resb(CUR, CUR, 3, c1 + 1536);
    cudaMemcpyAsync(E4, CUR, NB, cudaMemcpyDeviceToDevice);

    resb(CUR, CUR, 4, c2); mfe(2);
    mapmul_kernel<<<EG, 256>>>(CUR, mp);
    resb(CUR, CUR, 4, c2);
    add_kernel<<<EG, 256>>>(CUR, E4);

    for (int k = 0; k < 3; k++) resb(CUR, CUR, 5, c1 + 5 * 512);

    add_kernel<<<EG, 256>>>(CUR, E3);
    resb(CUR, CUR, 6, c1 + 6 * 512); mfe(3); resb(CUR, CUR, 6, c1 + 6 * 512);

    add_kernel<<<EG, 256>>>(CUR, E2);
    for (int k = 0; k < 3; k++) resb(CUR, CUR, 7, c1 + 7 * 512);

    add_kernel<<<EG, 256>>>(CUR, E1);
    resb(CUR, CUR, 8, c1 + 8 * 512);
    mfe(4);
    {
        const char* wp = W3P + (size_t)(8 * 2) * 18 * 8192;
        const float* bi = rb + (size_t)8 * 2 * 64;
        const float* cond = c1 + 8 * 512;
        launch_conv<3, 16, 1, 1, 0>(CUR, wp, bi, cond, nullptr, TMP);
        launch_conv<3, 16, 1, 0, 1>(TMP, wp + 18 * 8192, bi + 64, cond + 256, CUR, OUT);
    }
}

// round 9
// speedup vs baseline: 1.0866x; 1.0798x over previous
#include <cuda_runtime.h>
#include <cuda_bf16.h>
#include <cstdint>
#include <math.h>

#define HW    16384
#define CHW   1048576
#define NTOT  4194304

__device__ float g_buf[9][NTOT];
__device__ float g_mx[256];
__device__ float g_av[256];
__device__ float g_cf[256];
__device__ __align__(16) char g_w3pack[28 * 9 * 16384];
__device__ __align__(16) char g_w5pack[10 * 25 * 16384];

#define SWZ128(o) ((o) ^ (((o) >> 3) & 0x70))

__device__ __forceinline__ uint32_t smem_u32(const void* p) {
    uint32_t a;
    asm("{ .reg .u64 t; cvta.to.shared.u64 t, %1; cvt.u32.u64 %0, t; }" : "=r"(a) : "l"(p));
    return a;
}
#define LDMX4(r, addr) \
    asm volatile("ldmatrix.sync.aligned.m8n8.x4.shared.b16 {%0,%1,%2,%3}, [%4];" \
        : "=r"((r)[0]), "=r"((r)[1]), "=r"((r)[2]), "=r"((r)[3]) : "r"(addr))
#define MMA16816(c, a, b) \
    asm volatile("mma.sync.aligned.m16n8k16.row.col.f32.bf16.bf16.f32 " \
        "{%0,%1,%2,%3}, {%4,%5,%6,%7}, {%8,%9}, {%0,%1,%2,%3};" \
        : "+f"((c)[0]), "+f"((c)[1]), "+f"((c)[2]), "+f"((c)[3]) \
        : "r"((a)[0]), "r"((a)[1]), "r"((a)[2]), "r"((a)[3]), "r"((b)[0]), "r"((b)[1]))
#define CPASYNC16(dst, src) \
    asm volatile("cp.async.ca.shared.global [%0], [%1], 16;" :: "r"(dst), "l"(src))
#define CPCOMMIT() asm volatile("cp.async.commit_group;")

// ---------------- weight prep: hi/lo bf16, swizzled tile image per tap ----------------
__global__ void prep3_kernel(const float* __restrict__ rw, const float* __restrict__ w3,
                             char* __restrict__ dst)
{
    const int t = blockIdx.x, c = blockIdx.y;
    const float* w = (c < 18) ? (rw + (size_t)c * 36864) : (w3 + (size_t)(c - 18) * 36864);
    const float scale = (c < 18) ? (1.0f / 24.0f) : 1.0f;
    char* d = dst + ((size_t)c * 9 + t) * 16384;
    for (int e = threadIdx.x; e < 4096; e += 256) {
        int oc = e >> 6, ic = e & 63;
        float v = w[(oc * 64 + ic) * 9 + t] * scale;
        __nv_bfloat16 h = __float2bfloat16(v);
        __nv_bfloat16 l = __float2bfloat16(v - __bfloat162float(h));
        uint32_t off = SWZ128((uint32_t)(oc * 128 + ic * 2));
        *(unsigned short*)(d + off)        = __bfloat16_as_ushort(h);
        *(unsigned short*)(d + 8192 + off) = __bfloat16_as_ushort(l);
    }
}
__global__ void prep5_kernel(const float* __restrict__ w5, char* __restrict__ dst)
{
    const int t = blockIdx.x, c = blockIdx.y;
    const float* w = w5 + (size_t)c * 102400;
    char* d = dst + ((size_t)c * 25 + t) * 16384;
    for (int e = threadIdx.x; e < 4096; e += 256) {
        int oc = e >> 6, ic = e & 63;
        float v = w[(oc * 64 + ic) * 25 + t];
        __nv_bfloat16 h = __float2bfloat16(v);
        __nv_bfloat16 l = __float2bfloat16(v - __bfloat162float(h));
        uint32_t off = SWZ128((uint32_t)(oc * 128 + ic * 2));
        *(unsigned short*)(d + off)        = __bfloat16_as_ushort(h);
        *(unsigned short*)(d + 8192 + off) = __bfloat16_as_ushort(l);
    }
}

// ---------------------------------------------------------------------------
// bf16 HMMA conv (KDIM 3 or 5), pad=KDIM/2.  Tile: 16 wide x TH high.
// 512 thr = 16 warps: wm = warp&7 (M), wn = warp>>3 (N: 32 oc each).
// MPW = TH/8 m16-fragments/warp, processed in PAIRS with 3-pass MMA ordering
// (all Ah*Bh, then all Ah*Bl, then all Al*Bh) so same-accumulator MMAs are
// >=8 apart — hides HMMA latency.  Weights: 4-deep cp.async ring, 1 barrier/tap.
// ---------------------------------------------------------------------------
template<int KDIM, int TH, int MOD, int ACT, int RES>
__global__ void __launch_bounds__(512, 1) convMMA_kernel(
    const float* __restrict__ x, const char* __restrict__ wpack,
    const float* __restrict__ bias, const float* __restrict__ cond,
    const float* __restrict__ res, float* __restrict__ out)
{
    constexpr int TAPS = KDIM * KDIM;
    constexpr int HALO = KDIM / 2;
    constexpr int IW = 16 + 2 * HALO;
    constexpr int IH = TH + 2 * HALO;
    constexpr int NR = IH * IW;
    constexpr int MPW = TH / 8;
    constexpr int NPAIR = MPW / 2;

    extern __shared__ __align__(16) char sm[];
    char* actH = sm;
    char* actL = sm + NR * 128;
    char* wts  = sm + 2 * NR * 128;   // 4 x 16KB ring

    const int tid = threadIdx.x, lane = tid & 31, warp = tid >> 5;
    const int wm = warp & 7, wn = warp >> 3;
    const int gx0 = blockIdx.x * 16, gy0 = blockIdx.y * TH, b = blockIdx.z;
    const int cb = b * 64;
    const float* xb = x + (size_t)b * CHW;

    // ---- stage activation halo tile as bf16 hi/lo (swizzled 128B rows) ----
    for (int e = tid; e < 32 * NR; e += 512) {
        int j = e / NR, p = e - j * NR;
        int iy = p / IW, ix = p - iy * IW;
        int gy = gy0 + iy - HALO, gx = gx0 + ix - HALO;
        float v0 = 0.f, v1 = 0.f;
        if ((unsigned)gy < 128u && (unsigned)gx < 128u) {
            const float* q = xb + (size_t)(2 * j) * HW + gy * 128 + gx;
            v0 = q[0]; v1 = q[HW];
            if (MOD) { v0 *= cond[cb + 2 * j]; v1 *= cond[cb + 2 * j + 1]; }
        }
        __nv_bfloat16 h0 = __float2bfloat16(v0), h1 = __float2bfloat16(v1);
        __nv_bfloat16 l0 = __float2bfloat16(v0 - __bfloat162float(h0));
        __nv_bfloat16 l1 = __float2bfloat16(v1 - __bfloat162float(h1));
        uint32_t off = (uint32_t)p * 128 + ((4u * j) ^ ((uint32_t)(p & 7) << 4));
        *(uint32_t*)(actH + off) = ((uint32_t)__bfloat16_as_ushort(h1) << 16) | __bfloat16_as_ushort(h0);
        *(uint32_t*)(actL + off) = ((uint32_t)__bfloat16_as_ushort(l1) << 16) | __bfloat16_as_ushort(l0);
    }

    const uint32_t actHa = smem_u32(actH);
    const uint32_t actLa = smem_u32(actL);
    const uint32_t wtsA  = smem_u32(wts);

    auto prefetch = [&](int tap) {
        const char* src = wpack + (size_t)tap * 16384;
        uint32_t dst = wtsA + (uint32_t)(tap & 3) * 16384u;
#pragma unroll
        for (int i = 0; i < 2; i++)
            CPASYNC16(dst + (tid + i * 512) * 16, src + (tid + i * 512) * 16);
        CPCOMMIT();
    };
    prefetch(0); prefetch(1); prefetch(2);

    float c[MPW][4][4];
#pragma unroll
    for (int mi = 0; mi < MPW; mi++)
#pragma unroll
        for (int ni = 0; ni < 4; ni++)
#pragma unroll
            for (int k = 0; k < 4; k++) c[mi][ni][k] = 0.f;

    const int asub = lane >> 3;
    const int arow = ((asub & 1) << 3) + (lane & 7);
    const int ack  = asub >> 1;
    const int bmat = lane >> 3;
    const int bocl = ((bmat >> 1) << 3) + (lane & 7);
    const int bck  = bmat & 1;

    for (int t = 0; t < TAPS; ++t) {
        if (t <= TAPS - 3)      asm volatile("cp.async.wait_group 2;");
        else if (t == TAPS - 2) asm volatile("cp.async.wait_group 1;");
        else                    asm volatile("cp.async.wait_group 0;");
        __syncthreads();               // tap-t weights ready; buf (t-1)&3 free of readers
        if (t + 3 < TAPS) prefetch(t + 3);

        const int ky = t / KDIM, kx = t - ky * KDIM;
        const uint32_t wb = wtsA + (uint32_t)(t & 3) * 16384u;

#pragma unroll
        for (int ks = 0; ks < 4; ++ks) {
            uint32_t BH[4][2], BL[4][2];
#pragma unroll
            for (int gg = 0; gg < 2; ++gg) {
                int ocr = wn * 32 + gg * 16 + bocl;
                uint32_t base = (uint32_t)ocr * 128;
                uint32_t r[4];
                LDMX4(r, wb + base + ((uint32_t)((ks * 2 + bck) ^ (ocr & 7)) << 4));
                BH[gg * 2][0] = r[0]; BH[gg * 2][1] = r[1];
                BH[gg * 2 + 1][0] = r[2]; BH[gg * 2 + 1][1] = r[3];
                LDMX4(r, wb + 8192 + base + ((uint32_t)((ks * 2 + bck) ^ (ocr & 7)) << 4));
                BL[gg * 2][0] = r[0]; BL[gg * 2][1] = r[1];
                BL[gg * 2 + 1][0] = r[2]; BL[gg * 2 + 1][1] = r[3];
            }
#pragma unroll
            for (int mp = 0; mp < NPAIR; ++mp) {
                uint32_t AH[2][4], AL[2][4];
#pragma unroll
                for (int u = 0; u < 2; ++u) {
                    int rp = (wm * MPW + mp * 2 + u + ky) * IW + arow + kx;
                    uint32_t off = (uint32_t)rp * 128 + ((uint32_t)((ks * 2 + ack) ^ (rp & 7)) << 4);
                    LDMX4(AH[u], actHa + off);
                    LDMX4(AL[u], actLa + off);
                }
                // pass 1: Ah*Bh (8 independent)
#pragma unroll
                for (int u = 0; u < 2; ++u)
#pragma unroll
                    for (int ni = 0; ni < 4; ++ni)
                        MMA16816(c[mp * 2 + u][ni], AH[u], BH[ni]);
                // pass 2: Ah*Bl
#pragma unroll
                for (int u = 0; u < 2; ++u)
#pragma unroll
                    for (int ni = 0; ni < 4; ++ni)
                        MMA16816(c[mp * 2 + u][ni], AH[u], BL[ni]);
                // pass 3: Al*Bh
#pragma unroll
                for (int u = 0; u < 2; ++u)
#pragma unroll
                    for (int ni = 0; ni < 4; ++ni)
                        MMA16816(c[mp * 2 + u][ni], AL[u], BH[ni]);
            }
        }
    }

    // ---- epilogue ----
    const int r0 = lane >> 2, q2 = (lane & 3) * 2;
#pragma unroll
    for (int mi = 0; mi < MPW; ++mi) {
        const int y = wm * MPW + mi;
#pragma unroll
        for (int half = 0; half < 2; ++half) {
            const int xcol = r0 + half * 8;
            const int sp = (gy0 + y) * 128 + gx0 + xcol;
#pragma unroll
            for (int ni = 0; ni < 4; ++ni) {
#pragma unroll
                for (int dq = 0; dq < 2; ++dq) {
                    const int n = wn * 32 + ni * 8 + q2 + dq;
                    float v = c[mi][ni][half * 2 + dq];
                    v += MOD ? __ldg(&bias[(cb + n) >> 2]) : __ldg(&bias[n]);
                    if (ACT == 1) v = fmaxf(v, 0.f);
                    if (ACT == 2) v = v > 0.f ? v : 0.01f * v;
                    if (RES) v += __ldg(&res[(size_t)(cb + n) * HW + sp]);
                    out[(size_t)(cb + n) * HW + sp] = v;
                }
            }
        }
    }
}

// ---------------- fp32 1x1 conv ----------------
template<int ACT>
__global__ void __launch_bounds__(256) conv1_kernel(
    const float* __restrict__ x, const float* __restrict__ w,
    const float* __restrict__ bias, float* __restrict__ out)
{
    __shared__ float xs[64][64];
    __shared__ __align__(16) float ws[64][68];
    const int tid = threadIdx.x;
    const int b  = blockIdx.y;
    const int p0 = blockIdx.x * 64;
    for (int e = tid; e < 4096; e += 256) {
        int ic = e >> 6, px = e & 63;
        xs[ic][px] = x[(size_t)b * CHW + ic * HW + p0 + px];
    }
    for (int e = tid; e < 4096; e += 256) {
        int ocw = e >> 6, ic = e & 63;
        ws[ic][ocw] = w[ocw * 64 + ic];
    }
    __syncthreads();
    const int px = tid & 63;
    const int oc0 = (tid >> 6) * 16;
    float acc[16];
#pragma unroll
    for (int o = 0; o < 16; o++) acc[o] = 0.f;
#pragma unroll 4
    for (int ic = 0; ic < 64; ic++) {
        float xv = xs[ic][px];
        const float4* wr = (const float4*)&ws[ic][oc0];
        float4 w0 = wr[0], w1 = wr[1], w2 = wr[2], w3 = wr[3];
        acc[0]+=xv*w0.x; acc[1]+=xv*w0.y; acc[2]+=xv*w0.z; acc[3]+=xv*w0.w;
        acc[4]+=xv*w1.x; acc[5]+=xv*w1.y; acc[6]+=xv*w1.z; acc[7]+=xv*w1.w;
        acc[8]+=xv*w2.x; acc[9]+=xv*w2.y; acc[10]+=xv*w2.z; acc[11]+=xv*w2.w;
        acc[12]+=xv*w3.x; acc[13]+=xv*w3.y; acc[14]+=xv*w3.z; acc[15]+=xv*w3.w;
    }
#pragma unroll
    for (int o = 0; o < 16; o++) {
        float v = acc[o] + bias[oc0 + o];
        if (ACT == 2) v = v > 0.f ? v : 0.01f * v;
        out[(size_t)b * CHW + (oc0 + o) * HW + p0 + px] = v;
    }
}

// ---------------- small kernels ----------------
__global__ void pool_kernel(const float* __restrict__ x, float* __restrict__ mx, float* __restrict__ av)
{
    const int bc = blockIdx.x;
    const float* p = x + (size_t)bc * HW;
    float m = -3.402823466e38f, s = 0.f;
    for (int i = threadIdx.x; i < HW; i += 256) { float v = p[i]; m = fmaxf(m, v); s += v; }
#pragma unroll
    for (int o = 16; o; o >>= 1) {
        m = fmaxf(m, __shfl_xor_sync(0xFFFFFFFFu, m, o));
        s += __shfl_xor_sync(0xFFFFFFFFu, s, o);
    }
    __shared__ float sm_[8], ss_[8];
    int wid = threadIdx.x >> 5;
    if ((threadIdx.x & 31) == 0) { sm_[wid] = m; ss_[wid] = s; }
    __syncthreads();
    if (threadIdx.x == 0) {
        float mm = sm_[0], st = ss_[0];
        for (int i = 1; i < 8; i++) { mm = fmaxf(mm, sm_[i]); st += ss_[i]; }
        mx[bc] = mm; av[bc] = st * (1.0f / 16384.0f);
    }
}
__global__ void coef_kernel(const float* __restrict__ mx, const float* __restrict__ av,
                            const float* __restrict__ cw1, const float* __restrict__ cw2,
                            const float* __restrict__ fw, const float* __restrict__ fb,
                            float* __restrict__ coef)
{
    __shared__ float hm[16], ha[16];
    int t = threadIdx.x;
    if (t < 32) {
        int which = t >> 4, t2 = t & 15, b = t2 >> 2, j = t2 & 3;
        const float* v = which ? av : mx;
        float s = 0.f;
        for (int c = 0; c < 64; c++) s += v[b * 64 + c] * cw1[j * 64 + c];
        s = fmaxf(s, 0.f);
        if (which) ha[t2] = s; else hm[t2] = s;
    }
    __syncthreads();
    int b = t >> 6, c = t & 63;
    float se_m = 0.f, se_a = 0.f;
#pragma unroll
    for (int j = 0; j < 4; j++) {
        se_m += hm[b * 4 + j] * cw2[c * 4 + j];
        se_a += ha[b * 4 + j] * cw2[c * 4 + j];
    }
    float xll = 1.f / (1.f + expf(-(se_m + se_a)));
    coef[t] = fw[1] * (fw[0] * xll + fb[0]) + fb[1];
}
__global__ void combine_kernel(const float* __restrict__ s1, const float* __restrict__ s3,
                               const float* __restrict__ s5, const float* __restrict__ coef,
                               float* __restrict__ out)
{
    int fi = (blockIdx.x * 256 + threadIdx.x) * 4;
    float cf = coef[fi >> 14];
    float4 a = *(const float4*)(s1 + fi);
    float4 b = *(const float4*)(s3 + fi);
    float4 c = *(const float4*)(s5 + fi);
    float4 r;
    r.x = cf * (a.x + b.x + c.x); r.y = cf * (a.y + b.y + c.y);
    r.z = cf * (a.z + b.z + c.z); r.w = cf * (a.w + b.w + c.w);
    *(float4*)(out + fi) = r;
}
__global__ void add_kernel(float* __restrict__ a, const float* __restrict__ b)
{
    int fi = (blockIdx.x * 256 + threadIdx.x) * 4;
    float4 u = *(float4*)(a + fi);
    float4 v = *(const float4*)(b + fi);
    u.x += v.x; u.y += v.y; u.z += v.z; u.w += v.w;
    *(float4*)(a + fi) = u;
}
__global__ void mapmul_kernel(float* __restrict__ a, const float* __restrict__ mp)
{
    int fi = (blockIdx.x * 256 + threadIdx.x) * 4;
    int b = fi >> 20, s = fi & (HW - 1);
    float4 m = *(const float4*)(mp + b * HW + s);
    float4 v = *(float4*)(a + fi);
    v.x *= (1.f + m.x); v.y *= (1.f + m.y); v.z *= (1.f + m.z); v.w *= (1.f + m.w);
    *(float4*)(a + fi) = v;
}

// ---------------- launch ----------------
template<int KDIM, int TH, int MOD, int ACT, int RES>
static void launch_conv(const float* x, const char* wp, const float* bias,
                        const float* cond, const float* res, float* out)
{
    constexpr int HALO = KDIM / 2;
    constexpr int NR = (TH + 2 * HALO) * (16 + 2 * HALO);
    constexpr int SMEMB = 2 * NR * 128 + 4 * 16384;
    cudaFuncSetAttribute(convMMA_kernel<KDIM, TH, MOD, ACT, RES>,
                         cudaFuncAttributeMaxDynamicSharedMemorySize, SMEMB);
    convMMA_kernel<KDIM, TH, MOD, ACT, RES><<<dim3(8, 128 / TH, 4), 512, SMEMB>>>(x, wp, bias, cond, res, out);
}

extern "C" void kernel_launch(void* const* d_in, const int* in_sizes, int n_in,
                              void* d_out, int out_size)
{
    (void)in_sizes; (void)n_in; (void)out_size;
    const float* x   = (const float*)d_in[0];
    const float* c1  = (const float*)d_in[1];
    const float* c2  = (const float*)d_in[2];
    const float* mp  = (const float*)d_in[3];
    const float* rw  = (const float*)d_in[4];
    const float* rb  = (const float*)d_in[5];
    const float* w1  = (const float*)d_in[6];
    const float* b1  = (const float*)d_in[7];
    const float* w3  = (const float*)d_in[8];
    const float* b3  = (const float*)d_in[9];
    const float* w5  = (const float*)d_in[10];
    const float* b5  = (const float*)d_in[11];
    const float* cw1 = (const float*)d_in[12];
    const float* cw2 = (const float*)d_in[13];
    const float* fw  = (const float*)d_in[14];
    const float* fb  = (const float*)d_in[15];
    float* OUT = (float*)d_out;

    float* base;  cudaGetSymbolAddress((void**)&base, g_buf);
    char* W3P;    cudaGetSymbolAddress((void**)&W3P, g_w3pack);
    char* W5P;    cudaGetSymbolAddress((void**)&W5P, g_w5pack);
    float *MX, *AV, *CF;
    cudaGetSymbolAddress((void**)&MX, g_mx);
    cudaGetSymbolAddress((void**)&AV, g_av);
    cudaGetSymbolAddress((void**)&CF, g_cf);

    float* CUR = base;
    float* TMP = base + (size_t)NTOT;
    float* S1  = base + 2 * (size_t)NTOT;
    float* S3  = base + 3 * (size_t)NTOT;
    float* S5  = base + 4 * (size_t)NTOT;
    float* E1  = base + 5 * (size_t)NTOT;
    float* E2  = base + 6 * (size_t)NTOT;
    float* E3  = base + 7 * (size_t)NTOT;
    float* E4  = base + 8 * (size_t)NTOT;

    prep3_kernel<<<dim3(9, 28), 256>>>(rw, w3, W3P);
    prep5_kernel<<<dim3(25, 10), 256>>>(w5, W5P);

    const dim3 G1(256, 4);
    const int EG = NTOT / 4 / 256;

    auto resb = [&](const float* in, float* out, int i, const float* cond) {
        const char* wp = W3P + (size_t)(i * 2) * 9 * 16384;
        const float* bi = rb + (size_t)i * 2 * 64;
        launch_conv<3, 32, 1, 1, 0>(in, wp, bi, cond, nullptr, TMP);
        launch_conv<3, 32, 1, 0, 1>(TMP, wp + 9 * 16384, bi + 64, cond + 256, in, out);
    };
    auto mfe = [&](int i) {
        pool_kernel<<<256, 256>>>(CUR, MX, AV);
        coef_kernel<<<1, 256>>>(MX, AV, cw1 + i * 256, cw2 + i * 256, fw + i * 2, fb + i * 2, CF);
        const float* w1i = w1 + (size_t)i * 2 * 64 * 64;
        const char* w3p = W3P + (size_t)(18 + i * 2) * 9 * 16384;
        const char* w5p = W5P + (size_t)(i * 2) * 25 * 16384;
        conv1_kernel<2><<<G1, 256>>>(CUR, w1i, b1 + i * 128, TMP);
        conv1_kernel<0><<<G1, 256>>>(TMP, w1i + 64 * 64, b1 + i * 128 + 64, S1);
        launch_conv<3, 32, 0, 2, 0>(CUR, w3p, b3 + i * 128, nullptr, nullptr, TMP);
        launch_conv<3, 32, 0, 0, 0>(TMP, w3p + 9 * 16384, b3 + i * 128 + 64, nullptr, nullptr, S3);
        launch_conv<5, 16, 0, 2, 0>(CUR, w5p, b5 + i * 128, nullptr, nullptr, TMP);
        launch_conv<5, 16, 0, 0, 0>(TMP, w5p + 25 * 16384, b5 + i * 128 + 64, nullptr, nullptr, S5);
        combine_kernel<<<EG, 256>>>(S1, S3, S5, CF, CUR);
    };

    const size_t NB = (size_t)NTOT * sizeof(float);

    resb(x, CUR, 0, c1); mfe(0); resb(CUR, CUR, 0, c1);
    cudaMemcpyAsync(E1, CUR, NB, cudaMemcpyDeviceToDevice);

    for (int k = 0; k < 3; k++) resb(CUR, CUR, 1, c1 + 512);
    cudaMemcpyAsync(E2, CUR, NB, cudaMemcpyDeviceToDevice);

    resb(CUR, CUR, 2, c1 + 1024); mfe(1); resb(CUR, CUR, 2, c1 + 1024);
    cudaMemcpyAsync(E3, CUR, NB, cudaMemcpyDeviceToDevice);

    for (int k = 0; k < 3; k++) resb(CUR, CUR, 3, c1 + 1536);
    cudaMemcpyAsync(E4, CUR, NB, cudaMemcpyDeviceToDevice);

    resb(CUR, CUR, 4, c2); mfe(2);
    mapmul_kernel<<<EG, 256>>>(CUR, mp);
    resb(CUR, CUR, 4, c2);
    add_kernel<<<EG, 256>>>(CUR, E4);

    for (int k = 0; k < 3; k++) resb(CUR, CUR, 5, c1 + 5 * 512);

    add_kernel<<<EG, 256>>>(CUR, E3);
    resb(CUR, CUR, 6, c1 + 6 * 512); mfe(3); resb(CUR, CUR, 6, c1 + 6 * 512);

    add_kernel<<<EG, 256>>>(CUR, E2);
    for (int k = 0; k < 3; k++) resb(CUR, CUR, 7, c1 + 7 * 512);

    add_kernel<<<EG, 256>>>(CUR, E1);
    resb(CUR, CUR, 8, c1 + 8 * 512);
    mfe(4);
    {
        const char* wp = W3P + (size_t)(8 * 2) * 9 * 16384;
        const float* bi = rb + (size_t)8 * 2 * 64;
        const float* cond = c1 + 8 * 512;
        launch_conv<3, 32, 1, 1, 0>(CUR, wp, bi, cond, nullptr, TMP);
        launch_conv<3, 32, 1, 0, 1>(TMP, wp + 9 * 16384, bi + 64, cond + 256, CUR, OUT);
    }
}